// round 5
// baseline (speedup 1.0000x reference)
#include <cuda_runtime.h>
#include <cuda_bf16.h>

// FusionLoss: scalar loss over B=256 batches, K=16 keypoints.
// Inputs (metadata order):
//   d_in[0] output f32 [256,1,256,256]  (only 4096 gathered elements used)
//   d_in[1] mask   i32 [256,16]
//   d_in[2] ind    i32 [256,16]
//   d_in[3] target f32 [256,16,1]
//   d_in[4] gt_2d  f32 [256,32]
// Output: 1 float.
//
// 32 blocks x 128 threads; each warp owns TWO samples (lanes 0-15 sample A,
// lanes 16-31 sample B; xy held as float2 per lane). All reductions are
// 16-lane segmented butterflies; per-sample var gating happens before the
// halves merge. Cross-block combine: relaxed float REDGs + acq_rel ticket.

#define B    256
#define K    16
#define HW   65536
#define NE   12
#define SPW  2                        // samples per warp
#define WPB  4                        // warps per block
#define SPB  (SPW * WPB)              // 8 samples per block
#define NBLK (B / SPB)                // 32 blocks

static __constant__ int   c_ID1[NE] = {0, 1, 3, 4, 10, 11, 13, 14, 2, 3, 12, 13};
static __constant__ int   c_ID2[NE] = {1, 2, 4, 5, 11, 12, 14, 15, 6, 6, 8, 8};
static __constant__ float c_WGT[NE] = {
    1.0085885098415446f, 1.0f, 1.0f, 1.0085885098415446f,
    1.1375361376887123f, 1.0f, 1.0f, 1.1375361376887123f,
    1.0f, 1.0f, 1.0f, 1.0f};

// Device-global scratch (no allocation allowed). Zero at load; finisher
// re-zeros each call so graph replays are identical.
__device__ float        g_acc_sl1 = 0.0f;
__device__ float        g_acc_num = 0.0f;
__device__ float        g_acc_var = 0.0f;
__device__ unsigned int g_ticket  = 0;

__global__ __launch_bounds__(128, 8)
void fusion_loss_kernel(const float* __restrict__ output,
                        const int*   __restrict__ mask,
                        const int*   __restrict__ ind,
                        const float* __restrict__ target,
                        const float* __restrict__ gt2d,
                        float*       __restrict__ out)
{
    const int warp = threadIdx.x >> 5;
    const int lane = threadIdx.x & 31;
    const int sub  = lane & 15;            // keypoint index within sample
    const int hbase = lane & 16;           // 0 for sample A lanes, 16 for B
    const int s    = blockIdx.x * SPB + warp * SPW + (lane >> 4);  // sample id
    const unsigned FULL = 0xffffffffu;

    // ---- loads: every lane owns keypoint `sub` of sample `s` ----
    int   idx = __ldg(ind    + s * K + sub);
    float mk  = (float)__ldg(mask + s * K + sub);
    float tg  = __ldg(target + s * K + sub);
    float pred = __ldg(output + (size_t)s * HW + idx);      // random gather
    float2 xy  = __ldg((const float2*)(gt2d + s * 2 * K) + sub);

    // ---- smooth L1 partial ----
    float sl1 = 0.0f;
    if (mk != 0.0f) {
        float d  = pred - tg;
        float ad = fabsf(d);
        sl1 = (ad < 1.0f) ? 0.5f * ad * ad : (ad - 0.5f);
    }
    float msum = mk;

    // ---- 12-edge bone term: subs 0..11 own edge e = sub (per half-warp) ----
    // Edge->group map is contiguous: g0={0..3} g1={4..7} g2={8,9} g3={10,11}
    float le = 0.0f, visf = 0.0f;
    {
        int e  = (sub < NE) ? sub : 0;
        int i1 = c_ID1[e], i2 = c_ID2[e];
        float x1 = __shfl_sync(FULL, xy.x, hbase + i1);
        float y1 = __shfl_sync(FULL, xy.y, hbase + i1);
        float x2 = __shfl_sync(FULL, xy.x, hbase + i2);
        float y2 = __shfl_sync(FULL, xy.y, hbase + i2);
        float z1 = __shfl_sync(FULL, pred, hbase + i1);
        float z2 = __shfl_sync(FULL, pred, hbase + i2);
        float t1 = __shfl_sync(FULL, tg,   hbase + i1);
        float t2 = __shfl_sync(FULL, tg,   hbase + i2);
        if (sub < NE) {
            float dx = x1 - x2, dy = y1 - y2, dz = z1 - z2;
            le   = sqrtf(dx * dx + dy * dy + dz * dz) * c_WGT[sub];
            visf = ((t1 > 0.5f) && (t2 > 0.5f)) ? 1.0f : 0.0f;
        }
    }

    // ---- segmented butterfly for group sums (stays within each half) ----
    float sum_g = le * visf;
    float num_g = visf;
    {
        sum_g += __shfl_xor_sync(FULL, sum_g, 1);
        num_g += __shfl_xor_sync(FULL, num_g, 1);
        float s2 = __shfl_xor_sync(FULL, sum_g, 2);
        float n2 = __shfl_xor_sync(FULL, num_g, 2);
        if (sub < 8) { sum_g += s2; num_g += n2; }   // only the 4-wide groups
    }

    float term = 0.0f;
    if (sub < NE) {
        float ng = fmaxf(num_g, 1.0f);
        float Eg = (num_g > 0.5f) ? (sum_g / ng) : 0.0f;
        if (visf > 0.5f && le > 0.0f) {
            float d = le - Eg;
            term = d * d / (2.0f * ng);
        }
    }

    // ---- per-half (per-sample) butterfly: xor 8,4,2,1 stay within halves ----
#pragma unroll
    for (int sft = 8; sft > 0; sft >>= 1) {
        sl1  += __shfl_xor_sync(FULL, sl1,  sft);
        msum += __shfl_xor_sync(FULL, msum, sft);
        term += __shfl_xor_sync(FULL, term, sft);
    }
    // gate var PER SAMPLE, then merge the two halves
    float var = (msum == 0.0f) ? term : 0.0f;
    sl1  += __shfl_xor_sync(FULL, sl1,  16);
    msum += __shfl_xor_sync(FULL, msum, 16);
    var  += __shfl_xor_sync(FULL, var,  16);

    // ---- block combine (4 warps) in shared memory ----
    __shared__ float s_part[WPB][3];
    if (lane == 0) {
        s_part[warp][0] = sl1;
        s_part[warp][1] = msum;
        s_part[warp][2] = var;
    }
    __syncthreads();

    if (threadIdx.x == 0) {
        float a = 0.0f, n = 0.0f, v = 0.0f;
#pragma unroll
        for (int w = 0; w < WPB; w++) {
            a += s_part[w][0];
            n += s_part[w][1];
            v += s_part[w][2];
        }
        // relaxed fire-and-forget accumulator adds (REDG path)
        atomicAdd(&g_acc_sl1, a);
        atomicAdd(&g_acc_num, n);
        atomicAdd(&g_acc_var, v);
        // acq_rel ticket orders our REDGs before it and acquires the others'
        unsigned ticket;
        asm volatile("atom.add.acq_rel.gpu.global.u32 %0, [%1], %2;"
                     : "=r"(ticket)
                     : "l"(&g_ticket), "r"(1u)
                     : "memory");
        if (ticket == (unsigned)(NBLK - 1)) {
            float sa = *((volatile float*)&g_acc_sl1);
            float sn = *((volatile float*)&g_acc_num);
            float sv = *((volatile float*)&g_acc_var);
            float reg = sa / (sn + 0.0001f);
            out[0] = reg + 0.01f * (sv * (1.0f / (float)B));
            // reset for next graph replay (off the critical path)
            *((volatile float*)&g_acc_sl1) = 0.0f;
            *((volatile float*)&g_acc_num) = 0.0f;
            *((volatile float*)&g_acc_var) = 0.0f;
            *((volatile unsigned int*)&g_ticket) = 0u;
        }
    }
}

extern "C" void kernel_launch(void* const* d_in, const int* in_sizes, int n_in,
                              void* d_out, int out_size)
{
    const float* output = (const float*)d_in[0];
    const int*   mask   = (const int*)d_in[1];
    const int*   ind    = (const int*)d_in[2];
    const float* target = (const float*)d_in[3];
    const float* gt2d   = (const float*)d_in[4];
    float*       out    = (float*)d_out;

    fusion_loss_kernel<<<NBLK, 32 * WPB>>>(output, mask, ind, target, gt2d, out);
}